// round 6
// baseline (speedup 1.0000x reference)
#include <cuda_runtime.h>

#define BB 2
#define DD 160
#define HH 192
#define WW 160
#define NVOX (BB*DD*HH*WW)   // 9,830,400
#define KS 729.0f

// Scratch: 5 fields (W-sums), field-major: gA[f][b][d][h][w]
__device__ float gA[5 * NVOX];
__device__ double g_acc;          // static 0; reset by last block each run
__device__ unsigned int g_done;   // static 0; reset by last block each run

// ---------------------------------------------------------------------------
// Pass 1: along W. 8 rows/block, 256 threads, 5 consecutive outputs/thread
// via running W-sum (init 9 taps, then lead/trail increments).
// ---------------------------------------------------------------------------
__global__ __launch_bounds__(256) void k_pass1(const float* __restrict__ in,
                                               const float* __restrict__ tg) {
    __shared__ float sI[8][WW];
    __shared__ float sT[8][WW];
    const int tid = threadIdx.x;
    const size_t base = (size_t)blockIdx.x * 8 * WW;
#pragma unroll
    for (int i = 0; i < 5; ++i) {
        int idx = tid + i * 256;
        ((float*)sI)[idx] = in[base + idx];
        ((float*)sT)[idx] = (tg[base + idx] + 1.0f) * 0.5f;
    }
    __syncthreads();
    const int r = tid >> 5;
    const int l = tid & 31;
    const int w0 = l * 5;
    float s0 = 0.f, s1 = 0.f, s2 = 0.f, s3 = 0.f, s4 = 0.f;
#pragma unroll
    for (int j = -4; j <= 4; ++j) {
        int x = w0 + j;
        if (x >= 0 && x < WW) {
            float a = sI[r][x], b = sT[r][x];
            s0 += a; s1 += b; s2 += a * a; s3 += b * b; s4 += a * b;
        }
    }
    const size_t ob = base + (size_t)r * WW;
    gA[0 * (size_t)NVOX + ob + w0] = s0;
    gA[1 * (size_t)NVOX + ob + w0] = s1;
    gA[2 * (size_t)NVOX + ob + w0] = s2;
    gA[3 * (size_t)NVOX + ob + w0] = s3;
    gA[4 * (size_t)NVOX + ob + w0] = s4;
#pragma unroll
    for (int c = 1; c < 5; ++c) {
        int w = w0 + c;
        int wl = w + 4, wt = w - 5;
        float lI = (wl < WW) ? sI[r][wl] : 0.f;
        float lT = (wl < WW) ? sT[r][wl] : 0.f;
        float tI = (wt >= 0) ? sI[r][wt] : 0.f;
        float tT = (wt >= 0) ? sT[r][wt] : 0.f;
        s0 += lI - tI;
        s1 += lT - tT;
        s2 += lI * lI - tI * tI;
        s3 += lT * lT - tT * tT;
        s4 += lI * lT - tI * tT;
        gA[0 * (size_t)NVOX + ob + w] = s0;
        gA[1 * (size_t)NVOX + ob + w] = s1;
        gA[2 * (size_t)NVOX + ob + w] = s2;
        gA[3 * (size_t)NVOX + ob + w] = s3;
        gA[4 * (size_t)NVOX + ob + w] = s4;
    }
}

// ---------------------------------------------------------------------------
// Fused pass 2+3: block = 16 w x 16 d-groups x 2 d each (32 dd lanes, 24
// outputs). Walk H with per-thread running sums (lead/trail LDG prefetch).
// D-taps in smem, incremental second output. Last block writes the result.
// ---------------------------------------------------------------------------
#define WT 16
#define DG 16
#define KD 2
#define NDD (DG*KD)        // 32
#define DOUT 24
#define HCH 32
#define NT 256
#define BSTR 24            // buf row stride (floats): 2*24=48 ≡ 16 (mod 32)

__device__ __forceinline__ float cc_val(float r0, float r1, float r2, float r3, float r4) {
    const float inv = 1.0f / KS;
    float cross = r4 - r0 * r1 * inv;
    float T_var = r3 - r1 * r1 * inv;
    float I_var = r2 - r0 * r0 * inv;
    return cross * cross / (T_var * I_var + 1e-5f);
}

__global__ __launch_bounds__(NT) void k_pass23(float* __restrict__ out) {
    __shared__ float buf[2][5][NDD][BSTR];

    const int tid = threadIdx.x;
    const int tx = tid & (WT - 1);
    const int dg = tid >> 4;           // 0..15
    const int w0 = blockIdx.x * WT;
    const int dtile = blockIdx.y * DOUT;
    const int hchunks = HH / HCH;      // 6
    const int b = blockIdx.z / hchunks;
    const int c0 = (blockIdx.z % hchunks) * HCH;

    const float* __restrict__ A = gA;
    const int dd0 = dg * KD;           // this thread's first dd lane

    bool din[KD];
    size_t gb[KD];
    float r0[KD], r1[KD], r2[KD], r3[KD], r4[KD];
    float l0[KD], l1[KD], l2[KD], l3[KD], l4[KD];
    float t0[KD], t1[KD], t2[KD], t3[KD], t4[KD];

#pragma unroll
    for (int k = 0; k < KD; ++k) {
        int d_in = dtile - 4 + dd0 + k;
        din[k] = (d_in >= 0 && d_in < DD);
        gb[k] = din[k] ? ((((size_t)b * DD + d_in) * HH) * WW + w0 + tx) : 0;
        r0[k] = r1[k] = r2[k] = r3[k] = r4[k] = 0.f;
    }

    // init running H-sum over planes [c0-5, c0+3]
#pragma unroll
    for (int k = 0; k < KD; ++k) {
        if (din[k]) {
            for (int h = c0 - 5; h <= c0 + 3; ++h) {
                if (h >= 0) {
                    size_t i = gb[k] + (size_t)h * WW;
                    r0[k] += A[i];
                    r1[k] += A[i + (size_t)NVOX];
                    r2[k] += A[i + 2 * (size_t)NVOX];
                    r3[k] += A[i + 3 * (size_t)NVOX];
                    r4[k] += A[i + 4 * (size_t)NVOX];
                }
            }
        }
    }
    // preload lead (c0+4) and trail (c0-5)
#pragma unroll
    for (int k = 0; k < KD; ++k) {
        int hl = c0 + 4, ht = c0 - 5;
        bool vl = din[k];                 // hl < HH always here
        bool vt = din[k] && ht >= 0;
        size_t il = gb[k] + (size_t)hl * WW, it = gb[k] + (size_t)ht * WW;
        l0[k] = vl ? A[il] : 0.f;
        l1[k] = vl ? A[il + (size_t)NVOX] : 0.f;
        l2[k] = vl ? A[il + 2 * (size_t)NVOX] : 0.f;
        l3[k] = vl ? A[il + 3 * (size_t)NVOX] : 0.f;
        l4[k] = vl ? A[il + 4 * (size_t)NVOX] : 0.f;
        t0[k] = vt ? A[it] : 0.f;
        t1[k] = vt ? A[it + (size_t)NVOX] : 0.f;
        t2[k] = vt ? A[it + 2 * (size_t)NVOX] : 0.f;
        t3[k] = vt ? A[it + 3 * (size_t)NVOX] : 0.f;
        t4[k] = vt ? A[it + 4 * (size_t)NVOX] : 0.f;
    }

    const bool dgout = (dg >= 2 && dg <= 13);   // dd0 in [4,26]
    float facc = 0.f;
    int p = 0;

    for (int c = c0; c < c0 + HCH; ++c) {
#pragma unroll
        for (int k = 0; k < KD; ++k) {
            r0[k] += l0[k] - t0[k];
            r1[k] += l1[k] - t1[k];
            r2[k] += l2[k] - t2[k];
            r3[k] += l3[k] - t3[k];
            r4[k] += l4[k] - t4[k];
            buf[p][0][dd0 + k][tx] = r0[k];
            buf[p][1][dd0 + k][tx] = r1[k];
            buf[p][2][dd0 + k][tx] = r2[k];
            buf[p][3][dd0 + k][tx] = r3[k];
            buf[p][4][dd0 + k][tx] = r4[k];
        }
        // prefetch for step c+1: lead h=c+5, trail h=c-4
#pragma unroll
        for (int k = 0; k < KD; ++k) {
            int hl = c + 5, ht = c - 4;
            bool vl = din[k] && hl < HH;
            bool vt = din[k] && ht >= 0;
            size_t il = gb[k] + (size_t)hl * WW, it = gb[k] + (size_t)ht * WW;
            l0[k] = vl ? A[il] : 0.f;
            l1[k] = vl ? A[il + (size_t)NVOX] : 0.f;
            l2[k] = vl ? A[il + 2 * (size_t)NVOX] : 0.f;
            l3[k] = vl ? A[il + 3 * (size_t)NVOX] : 0.f;
            l4[k] = vl ? A[il + 4 * (size_t)NVOX] : 0.f;
            t0[k] = vt ? A[it] : 0.f;
            t1[k] = vt ? A[it + (size_t)NVOX] : 0.f;
            t2[k] = vt ? A[it + 2 * (size_t)NVOX] : 0.f;
            t3[k] = vt ? A[it + 3 * (size_t)NVOX] : 0.f;
            t4[k] = vt ? A[it + 4 * (size_t)NVOX] : 0.f;
        }

        __syncthreads();

        if (dgout) {
            // box sum for dd0: 9 taps per field
            float s0 = 0.f, s1 = 0.f, s2 = 0.f, s3 = 0.f, s4 = 0.f;
#pragma unroll
            for (int j = 0; j < 9; ++j) {
                int q = dd0 - 4 + j;
                s0 += buf[p][0][q][tx];
                s1 += buf[p][1][q][tx];
                s2 += buf[p][2][q][tx];
                s3 += buf[p][3][q][tx];
                s4 += buf[p][4][q][tx];
            }
            if (dtile + dd0 - 4 < DD) facc += cc_val(s0, s1, s2, s3, s4);
            // incremental for dd0+1
            s0 += buf[p][0][dd0 + 5][tx] - buf[p][0][dd0 - 4][tx];
            s1 += buf[p][1][dd0 + 5][tx] - buf[p][1][dd0 - 4][tx];
            s2 += buf[p][2][dd0 + 5][tx] - buf[p][2][dd0 - 4][tx];
            s3 += buf[p][3][dd0 + 5][tx] - buf[p][3][dd0 - 4][tx];
            s4 += buf[p][4][dd0 + 5][tx] - buf[p][4][dd0 - 4][tx];
            if (dtile + dd0 - 3 < DD) facc += cc_val(s0, s1, s2, s3, s4);
        }
        p ^= 1;
    }

    // block reduction (promote to double)
    double acc = (double)facc;
#pragma unroll
    for (int off = 16; off; off >>= 1) acc += __shfl_down_sync(0xffffffffu, acc, off);
    __shared__ double sred[8];
    int lane = tid & 31;
    int wid = tid >> 5;
    if (lane == 0) sred[wid] = acc;
    __syncthreads();
    if (wid == 0) {
        double a = (lane < 8) ? sred[lane] : 0.0;
#pragma unroll
        for (int off = 4; off; off >>= 1) a += __shfl_down_sync(0xffffffffu, a, off);
        if (lane == 0) {
            atomicAdd(&g_acc, a);
            __threadfence();
            unsigned int total = gridDim.x * gridDim.y * gridDim.z;
            unsigned int old = atomicAdd(&g_done, 1u);
            if (old == total - 1) {
                out[0] = (float)(-g_acc / (double)NVOX);
                g_acc = 0.0;
                g_done = 0u;
            }
        }
    }
}

extern "C" void kernel_launch(void* const* d_in, const int* in_sizes, int n_in,
                              void* d_out, int out_size) {
    const float* in = (const float*)d_in[0];
    const float* tg = (const float*)d_in[1];
    float* out = (float*)d_out;

    k_pass1<<<(BB * DD * HH) / 8, 256>>>(in, tg);
    {
        // 10 w-tiles x 7 d-tiles x (2 b x 6 h-chunks) = 840 blocks
        dim3 grid(WW / WT, (DD + DOUT - 1) / DOUT, BB * (HH / HCH));
        k_pass23<<<grid, NT>>>(out);
    }
}

// round 10
// speedup vs baseline: 1.8041x; 1.8041x over previous
#include <cuda_runtime.h>

#define BB 2
#define DD 160
#define HH 192
#define WW 160
#define NVOX (BB*DD*HH*WW)   // 9,830,400
#define KS 729.0f

// Scratch: 5 fields (W-sums), field-major: gA[f][b][d][h][w]
__device__ float gA[5 * NVOX];
__device__ double g_acc;          // static 0; reset by last block each run
__device__ unsigned int g_done;   // static 0; reset by last block each run

// ---------------------------------------------------------------------------
// Pass 1 (R5 version, proven): along W, 3 rows/block, 480 threads, coalesced.
// ---------------------------------------------------------------------------
__global__ void k_pass1(const float* __restrict__ in, const float* __restrict__ tg) {
    __shared__ float sI[3][WW];
    __shared__ float sT[3][WW];
    const int w = threadIdx.x;
    const int r = threadIdx.y;
    const size_t base = ((size_t)blockIdx.x * 3 + r) * WW;
    float iv = in[base + w];
    float tv = (tg[base + w] + 1.0f) * 0.5f;
    sI[r][w] = iv;
    sT[r][w] = tv;
    __syncthreads();
    float a0 = 0.f, a1 = 0.f, a2 = 0.f, a3 = 0.f, a4 = 0.f;
#pragma unroll
    for (int j = -4; j <= 4; ++j) {
        int x = w + j;
        if (x >= 0 && x < WW) {
            float a = sI[r][x], b = sT[r][x];
            a0 += a;
            a1 += b;
            a2 += a * a;
            a3 += b * b;
            a4 += a * b;
        }
    }
    gA[0 * (size_t)NVOX + base + w] = a0;
    gA[1 * (size_t)NVOX + base + w] = a1;
    gA[2 * (size_t)NVOX + base + w] = a2;
    gA[3 * (size_t)NVOX + base + w] = a3;
    gA[4 * (size_t)NVOX + base + w] = a4;
}

// ---------------------------------------------------------------------------
// Fused pass 2+3: 256 threads = 16 w x 16 d-groups x KD=2 d-columns.
// Walk H with running sums. Lead planes prefetched to regs; TRAIL planes
// loaded post-sync (L2 hits: same thread loaded them 9 steps ago as leads).
// D box-sum: 9 smem taps for first column, incremental (+2 taps/field) for
// the second. Bank-conflict-free via BSTR=24. Last block writes the result.
// ---------------------------------------------------------------------------
#define WT 16
#define DG 16
#define KD 2
#define NDD (DG*KD)        // 32
#define DOUT 24
#define HCH 32
#define NT 256
#define BSTR 24

__device__ __forceinline__ float cc_val(float r0, float r1, float r2, float r3, float r4) {
    const float inv = 1.0f / KS;
    float cross = r4 - r0 * r1 * inv;
    float T_var = r3 - r1 * r1 * inv;
    float I_var = r2 - r0 * r0 * inv;
    return cross * cross / (T_var * I_var + 1e-5f);
}

__global__ __launch_bounds__(NT) void k_pass23(float* __restrict__ out) {
    __shared__ float buf[2][5][NDD][BSTR];

    const int tid = threadIdx.x;
    const int tx = tid & (WT - 1);
    const int dg = tid >> 4;           // 0..15
    const int w0 = blockIdx.x * WT;
    const int dtile = blockIdx.y * DOUT;
    const int hchunks = HH / HCH;      // 6
    const int b = blockIdx.z / hchunks;
    const int c0 = (blockIdx.z % hchunks) * HCH;

    const float* __restrict__ A = gA;
    const int dd0 = dg * KD;

    bool din[KD];
    size_t gb[KD];
    float r0[KD], r1[KD], r2[KD], r3[KD], r4[KD];
    float l0[KD], l1[KD], l2[KD], l3[KD], l4[KD];

#pragma unroll
    for (int k = 0; k < KD; ++k) {
        int d_in = dtile - 4 + dd0 + k;
        din[k] = (d_in >= 0 && d_in < DD);
        gb[k] = din[k] ? ((((size_t)b * DD + d_in) * HH) * WW + w0 + tx) : 0;
        r0[k] = r1[k] = r2[k] = r3[k] = r4[k] = 0.f;
    }

    // init running H-sum over planes [c0-5, c0+3]
#pragma unroll
    for (int k = 0; k < KD; ++k) {
        if (din[k]) {
            for (int h = c0 - 5; h <= c0 + 3; ++h) {
                if (h >= 0) {
                    size_t i = gb[k] + (size_t)h * WW;
                    r0[k] += A[i];
                    r1[k] += A[i + (size_t)NVOX];
                    r2[k] += A[i + 2 * (size_t)NVOX];
                    r3[k] += A[i + 3 * (size_t)NVOX];
                    r4[k] += A[i + 4 * (size_t)NVOX];
                }
            }
        }
    }
    // preload lead plane (h = c0+4; always < HH for our chunking)
#pragma unroll
    for (int k = 0; k < KD; ++k) {
        size_t il = gb[k] + (size_t)(c0 + 4) * WW;
        l0[k] = din[k] ? A[il] : 0.f;
        l1[k] = din[k] ? A[il + (size_t)NVOX] : 0.f;
        l2[k] = din[k] ? A[il + 2 * (size_t)NVOX] : 0.f;
        l3[k] = din[k] ? A[il + 3 * (size_t)NVOX] : 0.f;
        l4[k] = din[k] ? A[il + 4 * (size_t)NVOX] : 0.f;
    }

    const bool dgout = (dg >= 2 && dg <= 13);   // dd0 in [4,26]
    float facc = 0.f;
    int p = 0;

    for (int c = c0; c < c0 + HCH; ++c) {
        // trail (h = c-5): L2 hit — this thread loaded it as lead 9 steps ago
#pragma unroll
        for (int k = 0; k < KD; ++k) {
            bool vt = din[k] && (c - 5 >= 0);
            size_t it = gb[k] + (size_t)(c - 5) * WW;
            float t0 = vt ? A[it] : 0.f;
            float t1 = vt ? A[it + (size_t)NVOX] : 0.f;
            float t2 = vt ? A[it + 2 * (size_t)NVOX] : 0.f;
            float t3 = vt ? A[it + 3 * (size_t)NVOX] : 0.f;
            float t4 = vt ? A[it + 4 * (size_t)NVOX] : 0.f;
            r0[k] += l0[k] - t0;
            r1[k] += l1[k] - t1;
            r2[k] += l2[k] - t2;
            r3[k] += l3[k] - t3;
            r4[k] += l4[k] - t4;
            buf[p][0][dd0 + k][tx] = r0[k];
            buf[p][1][dd0 + k][tx] = r1[k];
            buf[p][2][dd0 + k][tx] = r2[k];
            buf[p][3][dd0 + k][tx] = r3[k];
            buf[p][4][dd0 + k][tx] = r4[k];
        }
        // prefetch lead for step c+1 (h = c+5)
#pragma unroll
        for (int k = 0; k < KD; ++k) {
            bool vl = din[k] && (c + 5 < HH);
            size_t il = gb[k] + (size_t)(c + 5) * WW;
            l0[k] = vl ? A[il] : 0.f;
            l1[k] = vl ? A[il + (size_t)NVOX] : 0.f;
            l2[k] = vl ? A[il + 2 * (size_t)NVOX] : 0.f;
            l3[k] = vl ? A[il + 3 * (size_t)NVOX] : 0.f;
            l4[k] = vl ? A[il + 4 * (size_t)NVOX] : 0.f;
        }

        __syncthreads();

        if (dgout) {
            float s0 = 0.f, s1 = 0.f, s2 = 0.f, s3 = 0.f, s4 = 0.f;
#pragma unroll
            for (int j = 0; j < 9; ++j) {
                int q = dd0 - 4 + j;
                s0 += buf[p][0][q][tx];
                s1 += buf[p][1][q][tx];
                s2 += buf[p][2][q][tx];
                s3 += buf[p][3][q][tx];
                s4 += buf[p][4][q][tx];
            }
            if (dtile + dd0 - 4 < DD) facc += cc_val(s0, s1, s2, s3, s4);
            s0 += buf[p][0][dd0 + 5][tx] - buf[p][0][dd0 - 4][tx];
            s1 += buf[p][1][dd0 + 5][tx] - buf[p][1][dd0 - 4][tx];
            s2 += buf[p][2][dd0 + 5][tx] - buf[p][2][dd0 - 4][tx];
            s3 += buf[p][3][dd0 + 5][tx] - buf[p][3][dd0 - 4][tx];
            s4 += buf[p][4][dd0 + 5][tx] - buf[p][4][dd0 - 4][tx];
            if (dtile + dd0 - 3 < DD) facc += cc_val(s0, s1, s2, s3, s4);
        }
        p ^= 1;
    }

    // block reduction (promote to double)
    double acc = (double)facc;
#pragma unroll
    for (int off = 16; off; off >>= 1) acc += __shfl_down_sync(0xffffffffu, acc, off);
    __shared__ double sred[8];
    int lane = tid & 31;
    int wid = tid >> 5;
    if (lane == 0) sred[wid] = acc;
    __syncthreads();
    if (wid == 0) {
        double a = (lane < 8) ? sred[lane] : 0.0;
#pragma unroll
        for (int off = 4; off; off >>= 1) a += __shfl_down_sync(0xffffffffu, a, off);
        if (lane == 0) {
            atomicAdd(&g_acc, a);
            __threadfence();
            unsigned int total = gridDim.x * gridDim.y * gridDim.z;
            unsigned int old = atomicAdd(&g_done, 1u);
            if (old == total - 1) {
                out[0] = (float)(-g_acc / (double)NVOX);
                g_acc = 0.0;
                g_done = 0u;
            }
        }
    }
}

extern "C" void kernel_launch(void* const* d_in, const int* in_sizes, int n_in,
                              void* d_out, int out_size) {
    const float* in = (const float*)d_in[0];
    const float* tg = (const float*)d_in[1];
    float* out = (float*)d_out;

    {
        dim3 blk(WW, 3);
        k_pass1<<<(BB * DD * HH) / 3, blk>>>(in, tg);
    }
    {
        // 10 w-tiles x 7 d-tiles x (2 b x 6 h-chunks) = 840 blocks
        dim3 grid(WW / WT, (DD + DOUT - 1) / DOUT, BB * (HH / HCH));
        k_pass23<<<grid, NT>>>(out);
    }
}